// round 3
// baseline (speedup 1.0000x reference)
#include <cuda_runtime.h>
#include <cuda_bf16.h>
#include <math.h>

// Problem dims
static constexpr int BATCH = 16;
static constexpr int DIMD  = 512;
static constexpr int NN    = 2048;
static constexpr int NSAMP = 15;

// ---------------- scratch (device globals; no allocations allowed) ----------
__device__ float g_scores[(size_t)BATCH * NN * NN];   // 268 MB: logits then scores
__device__ float g_rowVal[BATCH * NN];
__device__ int   g_rowArg[BATCH * NN];
__device__ float g_colsum[BATCH * NN];
__device__ int   g_matchR[BATCH * NSAMP];
__device__ int   g_matchC[BATCH * NSAMP];

// ---------------- Kernel 1: batched GEMM  logits = (src_emb^T tgt_emb)/sqrt(D)
// A,B layout: [B, D, N] with N contiguous. logits[b,s,t] = sum_d A[b,d,s]*B[b,d,t]
// 128x128 tile, BK=8, 256 threads, 8x8 microtile, packed f32x2 FMA.
#define BM 128
#define BN 128
#define BK 8

__global__ __launch_bounds__(256) void gemm_logits_kernel(
    const float* __restrict__ A, const float* __restrict__ Bm)
{
    int b  = blockIdx.z;
    int s0 = blockIdx.y * BM;
    int t0 = blockIdx.x * BN;
    const float* Ab = A  + (size_t)b * DIMD * NN;
    const float* Bb = Bm + (size_t)b * DIMD * NN;
    float* Ob = g_scores + (size_t)b * NN * NN;

    __shared__ __align__(16) float As[BK][BM];
    __shared__ __align__(16) float Bs[BK][BN];

    int tid = threadIdx.x;
    int tx = tid & 15;       // 0..15 -> column group (8 cols each)
    int ty = tid >> 4;       // 0..15 -> row group (8 rows each)

    unsigned long long acc[8][4];
#pragma unroll
    for (int i = 0; i < 8; i++)
#pragma unroll
        for (int j = 0; j < 4; j++) acc[i][j] = 0ull;

    for (int k0 = 0; k0 < DIMD; k0 += BK) {
        // load 8x128 tiles of A and B (coalesced: N contiguous)
#pragma unroll
        for (int i = 0; i < 4; i++) {
            int idx = tid + i * 256;        // 0..1023
            int kk = idx >> 7;              // 0..7
            int ss = idx & 127;             // 0..127
            As[kk][ss] = Ab[(size_t)(k0 + kk) * NN + s0 + ss];
            Bs[kk][ss] = Bb[(size_t)(k0 + kk) * NN + t0 + ss];
        }
        __syncthreads();

#pragma unroll
        for (int k = 0; k < BK; k++) {
            unsigned long long bv[4];
            const unsigned long long* brow =
                reinterpret_cast<const unsigned long long*>(&Bs[k][tx * 8]);
#pragma unroll
            for (int j = 0; j < 4; j++) bv[j] = brow[j];

            const float4* ar = reinterpret_cast<const float4*>(&As[k][ty * 8]);
            float4 a0 = ar[0], a1 = ar[1];
            float av[8] = {a0.x, a0.y, a0.z, a0.w, a1.x, a1.y, a1.z, a1.w};
#pragma unroll
            for (int i = 0; i < 8; i++) {
                unsigned int ab = __float_as_uint(av[i]);
                unsigned long long ap = (((unsigned long long)ab) << 32) | ab;
#pragma unroll
                for (int j = 0; j < 4; j++) {
                    asm("fma.rn.f32x2 %0, %1, %2, %0;"
                        : "+l"(acc[i][j]) : "l"(ap), "l"(bv[j]));
                }
            }
        }
        __syncthreads();
    }

    const float scale = 0.044194173824159216f;  // 1/sqrt(512)
#pragma unroll
    for (int i = 0; i < 8; i++) {
        float v[8];
#pragma unroll
        for (int j = 0; j < 4; j++) {
            v[2 * j]     = __uint_as_float((unsigned)(acc[i][j] & 0xffffffffull)) * scale;
            v[2 * j + 1] = __uint_as_float((unsigned)(acc[i][j] >> 32)) * scale;
        }
        float* orow = Ob + (size_t)(s0 + ty * 8 + i) * NN + (t0 + tx * 8);
        reinterpret_cast<float4*>(orow)[0] = make_float4(v[0], v[1], v[2], v[3]);
        reinterpret_cast<float4*>(orow)[1] = make_float4(v[4], v[5], v[6], v[7]);
    }
}

// ---------------- Kernel 2: per-row softmax (in place) + row max/argmax of scores
__global__ __launch_bounds__(256) void softmax_kernel()
{
    int row = blockIdx.x;                       // 0 .. B*N-1
    float* p = g_scores + (size_t)row * NN;
    __shared__ float rv[256];
    __shared__ int   ri[256];
    int tid = threadIdx.x;

    // pass 1: row max of logits
    float m = -3.4e38f;
    for (int c = tid; c < NN; c += 256) { float v = p[c]; if (v > m) m = v; }
    rv[tid] = m; __syncthreads();
    for (int s = 128; s > 0; s >>= 1) {
        if (tid < s) { if (rv[tid + s] > rv[tid]) rv[tid] = rv[tid + s]; }
        __syncthreads();
    }
    float M = rv[0];
    __syncthreads();

    // pass 2: sum of exp
    float sum = 0.f;
    for (int c = tid; c < NN; c += 256) sum += expf(p[c] - M);
    rv[tid] = sum; __syncthreads();
    for (int s = 128; s > 0; s >>= 1) {
        if (tid < s) rv[tid] += rv[tid + s];
        __syncthreads();
    }
    float inv = 1.0f / rv[0];
    __syncthreads();

    // pass 3: write scores
    for (int c = tid; c < NN; c += 256) p[c] = expf(p[c] - M) * inv;
    __syncthreads();

    // pass 4: max/argmax of STORED scores (tie -> smallest col), for matching invariant
    float mv = -1.f; int mc = 0;
    for (int c = tid; c < NN; c += 256) { float v = p[c]; if (v > mv) { mv = v; mc = c; } }
    rv[tid] = mv; ri[tid] = mc; __syncthreads();
    for (int s = 128; s > 0; s >>= 1) {
        if (tid < s) {
            float v2 = rv[tid + s]; int c2 = ri[tid + s];
            if (v2 > rv[tid] || (v2 == rv[tid] && c2 < ri[tid])) { rv[tid] = v2; ri[tid] = c2; }
        }
        __syncthreads();
    }
    if (tid == 0) { g_rowVal[row] = rv[0]; g_rowArg[row] = ri[0]; }
}

// ---------------- Kernel 3: column sums of scores: colsum[b,t] = sum_s scores[b,s,t]
__global__ __launch_bounds__(256) void colsum_kernel()
{
    int b = blockIdx.y;
    int t = blockIdx.x * 256 + threadIdx.x;
    const float* sc = g_scores + (size_t)b * NN * NN;
    float s = 0.f;
    for (int r = 0; r < NN; r++) s += sc[(size_t)r * NN + t];
    g_colsum[b * NN + t] = s;
}

// ---------------- Kernel 4: greedy one-to-one matching (one block per batch)
__global__ __launch_bounds__(256) void match_kernel()
{
    int b = blockIdx.x;
    int tid = threadIdx.x;
    __shared__ float rVal[NN];
    __shared__ int   rArg[NN];
    __shared__ unsigned char colDead[NN];
    __shared__ float redV[256];
    __shared__ int   redI[256];
    __shared__ int   list[256];
    __shared__ int   listCnt;
    __shared__ int   selC;

    for (int i = tid; i < NN; i += 256) {
        rVal[i] = g_rowVal[b * NN + i];
        rArg[i] = g_rowArg[b * NN + i];
        colDead[i] = 0;
    }
    __syncthreads();

    const float* sc = g_scores + (size_t)b * NN * NN;

    for (int it = 0; it < NSAMP; it++) {
        // global argmax over alive rows (tie -> smallest row)
        float bv = -1.f; int br = 0;
        for (int r = tid; r < NN; r += 256) {
            float v = rVal[r];
            if (v > bv) { bv = v; br = r; }
        }
        redV[tid] = bv; redI[tid] = br; __syncthreads();
        for (int s = 128; s > 0; s >>= 1) {
            if (tid < s) {
                float v2 = redV[tid + s]; int r2 = redI[tid + s];
                if (v2 > redV[tid] || (v2 == redV[tid] && r2 < redI[tid])) {
                    redV[tid] = v2; redI[tid] = r2;
                }
            }
            __syncthreads();
        }
        if (tid == 0) {
            int r = redI[0];
            int c = rArg[r];
            g_matchR[b * NSAMP + it] = r;
            g_matchC[b * NSAMP + it] = c;
            rVal[r] = -1.f;           // kill row
            colDead[c] = 1;           // kill column
            selC = c;
            listCnt = 0;
        }
        __syncthreads();

        int c = selC;
        // rows whose cached argmax just died need a rescan
        for (int r = tid; r < NN; r += 256) {
            if (rVal[r] >= 0.f && rArg[r] == c) {
                int pos = atomicAdd(&listCnt, 1);
                if (pos < 256) list[pos] = r;
            }
        }
        __syncthreads();
        int cnt = listCnt; if (cnt > 256) cnt = 256;
        for (int li = 0; li < cnt; li++) {
            int r = list[li];
            const float* rowp = sc + (size_t)r * NN;
            float mv = -1.f; int mc = 0;
            for (int cc = tid; cc < NN; cc += 256) {
                if (!colDead[cc]) {
                    float v = rowp[cc];
                    if (v > mv) { mv = v; mc = cc; }
                }
            }
            redV[tid] = mv; redI[tid] = mc; __syncthreads();
            for (int s = 128; s > 0; s >>= 1) {
                if (tid < s) {
                    float v2 = redV[tid + s]; int c2 = redI[tid + s];
                    if (v2 > redV[tid] || (v2 == redV[tid] && c2 < redI[tid])) {
                        redV[tid] = v2; redI[tid] = c2;
                    }
                }
                __syncthreads();
            }
            if (tid == 0) { rVal[r] = redV[0]; rArg[r] = redI[0]; }
            __syncthreads();
        }
        __syncthreads();
    }
}

// ---------------- Kernel 5: gather + centroids + 3x3 Kabsch SVD + output
__global__ __launch_bounds__(128) void finalize_kernel(
    const float* __restrict__ src, const float* __restrict__ tgt,
    float* __restrict__ out, int out_size)
{
    int b = blockIdx.x, tid = threadIdx.x;
    __shared__ float rx[128], ry[128], rz[128];
    __shared__ float srcMean[3], corrMean[3];
    __shared__ float sp[NSAMP][3], tp[NSAMP][3];

    const float* sb = src + (size_t)b * NN * 3;  // src[b, n, i]
    const float* tb = tgt + (size_t)b * NN * 3;

    // mean of src points over all N
    float sx = 0, sy = 0, sz = 0;
    for (int n = tid; n < NN; n += 128) {
        sx += sb[3 * n]; sy += sb[3 * n + 1]; sz += sb[3 * n + 2];
    }
    rx[tid] = sx; ry[tid] = sy; rz[tid] = sz; __syncthreads();
    for (int s = 64; s > 0; s >>= 1) {
        if (tid < s) { rx[tid] += rx[tid + s]; ry[tid] += ry[tid + s]; rz[tid] += rz[tid + s]; }
        __syncthreads();
    }
    if (tid == 0) {
        srcMean[0] = rx[0] / NN; srcMean[1] = ry[0] / NN; srcMean[2] = rz[0] / NN;
    }
    __syncthreads();

    // src_corr.mean(axis=2) = (1/N) sum_t tgt[b,:,t] * colsum[b,t]
    sx = sy = sz = 0;
    for (int n = tid; n < NN; n += 128) {
        float w = g_colsum[b * NN + n];
        sx += tb[3 * n] * w; sy += tb[3 * n + 1] * w; sz += tb[3 * n + 2] * w;
    }
    rx[tid] = sx; ry[tid] = sy; rz[tid] = sz; __syncthreads();
    for (int s = 64; s > 0; s >>= 1) {
        if (tid < s) { rx[tid] += rx[tid + s]; ry[tid] += ry[tid + s]; rz[tid] += rz[tid + s]; }
        __syncthreads();
    }
    if (tid == 0) {
        corrMean[0] = rx[0] / NN; corrMean[1] = ry[0] / NN; corrMean[2] = rz[0] / NN;
    }

    // gather matched points
    if (tid < NSAMP) {
        int r = g_matchR[b * NSAMP + tid];
        int c = g_matchC[b * NSAMP + tid];
        sp[tid][0] = sb[3 * r]; sp[tid][1] = sb[3 * r + 1]; sp[tid][2] = sb[3 * r + 2];
        tp[tid][0] = tb[3 * c]; tp[tid][1] = tb[3 * c + 1]; tp[tid][2] = tb[3 * c + 2];
    }
    __syncthreads();

    if (tid == 0) {
        // centroids of matched sets
        double ms[3] = {0, 0, 0}, mt[3] = {0, 0, 0};
        for (int s = 0; s < NSAMP; s++)
            for (int i = 0; i < 3; i++) { ms[i] += sp[s][i]; mt[i] += tp[s][i]; }
        for (int i = 0; i < 3; i++) { ms[i] /= NSAMP; mt[i] /= NSAMP; }

        // H[i][j] = sum_s (sp-ms)_i (tp-mt)_j
        double H[3][3] = {};
        for (int s = 0; s < NSAMP; s++)
            for (int i = 0; i < 3; i++)
                for (int j = 0; j < 3; j++)
                    H[i][j] += ((double)sp[s][i] - ms[i]) * ((double)tp[s][j] - mt[j]);

        // S = H^T H  (symmetric), Jacobi eigendecomposition -> V, lambda
        double Sm[3][3];
        for (int i = 0; i < 3; i++)
            for (int j = 0; j < 3; j++) {
                double acc = 0;
                for (int k = 0; k < 3; k++) acc += H[k][i] * H[k][j];
                Sm[i][j] = acc;
            }
        double V[3][3] = {{1, 0, 0}, {0, 1, 0}, {0, 0, 1}};
        for (int sweep = 0; sweep < 12; sweep++) {
            for (int pi = 0; pi < 3; pi++) {
                for (int qi = pi + 1; qi < 3; qi++) {
                    double apq = Sm[pi][qi];
                    if (fabs(apq) < 1e-30) continue;
                    double app = Sm[pi][pi], aqq = Sm[qi][qi];
                    double theta = 0.5 * (aqq - app) / apq;
                    double tJ = ((theta >= 0) ? 1.0 : -1.0) /
                                (fabs(theta) + sqrt(theta * theta + 1.0));
                    double cJ = 1.0 / sqrt(tJ * tJ + 1.0);
                    double sJ = tJ * cJ;
                    for (int k = 0; k < 3; k++) {
                        double skp = Sm[k][pi], skq = Sm[k][qi];
                        Sm[k][pi] = cJ * skp - sJ * skq;
                        Sm[k][qi] = sJ * skp + cJ * skq;
                    }
                    for (int k = 0; k < 3; k++) {
                        double spk = Sm[pi][k], sqk = Sm[qi][k];
                        Sm[pi][k] = cJ * spk - sJ * sqk;
                        Sm[qi][k] = sJ * spk + cJ * sqk;
                    }
                    for (int k = 0; k < 3; k++) {
                        double vkp = V[k][pi], vkq = V[k][qi];
                        V[k][pi] = cJ * vkp - sJ * vkq;
                        V[k][qi] = sJ * vkp + cJ * vkq;
                    }
                }
            }
        }
        double lam[3] = {Sm[0][0], Sm[1][1], Sm[2][2]};
        // sort descending (matching jnp svd order)
        int idx[3] = {0, 1, 2};
        for (int i = 0; i < 2; i++)
            for (int j = i + 1; j < 3; j++)
                if (lam[idx[j]] > lam[idx[i]]) { int t2 = idx[i]; idx[i] = idx[j]; idx[j] = t2; }
        double Vc[3][3], U[3][3];
        for (int k = 0; k < 3; k++) {
            int c = idx[k];
            double sig = sqrt(lam[c] > 0 ? lam[c] : 0);
            double invs = (sig > 1e-300) ? 1.0 / sig : 0.0;
            for (int i = 0; i < 3; i++) Vc[i][k] = V[i][c];
            for (int i = 0; i < 3; i++) {
                double acc = 0;
                for (int j = 0; j < 3; j++) acc += H[i][j] * Vc[j][k];
                U[i][k] = acc * invs;
            }
        }
        // R = V U^T
        double R[3][3];
        for (int i = 0; i < 3; i++)
            for (int j = 0; j < 3; j++) {
                double acc = 0;
                for (int k = 0; k < 3; k++) acc += Vc[i][k] * U[j][k];
                R[i][j] = acc;
            }
        double det =
            R[0][0] * (R[1][1] * R[2][2] - R[1][2] * R[2][1]) -
            R[0][1] * (R[1][0] * R[2][2] - R[1][2] * R[2][0]) +
            R[0][2] * (R[1][0] * R[2][1] - R[1][1] * R[2][0]);
        if (det < 0) {
            for (int i = 0; i < 3; i++)
                for (int j = 0; j < 3; j++)
                    R[i][j] -= 2.0 * Vc[i][2] * U[j][2];
        }
        // t = -R @ srcMean + corrMean
        double tv[3];
        for (int i = 0; i < 3; i++) {
            double acc = 0;
            for (int j = 0; j < 3; j++) acc += R[i][j] * (double)srcMean[j];
            tv[i] = -acc + (double)corrMean[i];
        }
        // write: R rows-major [B,3,3] then t [B,3]
        for (int i = 0; i < 3; i++)
            for (int j = 0; j < 3; j++)
                out[b * 9 + i * 3 + j] = (float)R[i][j];
        if (out_size >= BATCH * 9 + BATCH * 3) {
            for (int i = 0; i < 3; i++)
                out[BATCH * 9 + b * 3 + i] = (float)tv[i];
        }
    }
}

// ---------------- launch ----------------
extern "C" void kernel_launch(void* const* d_in, const int* in_sizes, int n_in,
                              void* d_out, int out_size)
{
    const float* src_emb = (const float*)d_in[0];
    const float* tgt_emb = (const float*)d_in[1];
    const float* src     = (const float*)d_in[2];
    const float* tgt     = (const float*)d_in[3];
    float* out = (float*)d_out;

    dim3 gGemm(NN / BN, NN / BM, BATCH);
    gemm_logits_kernel<<<gGemm, 256>>>(src_emb, tgt_emb);

    softmax_kernel<<<BATCH * NN, 256>>>();

    dim3 gCol(NN / 256, BATCH);
    colsum_kernel<<<gCol, 256>>>();

    match_kernel<<<BATCH, 256>>>();

    finalize_kernel<<<BATCH, 128>>>(src, tgt, out, out_size);
}

// round 9
// speedup vs baseline: 1.9603x; 1.9603x over previous
#include <cuda_runtime.h>
#include <cuda_bf16.h>
#include <math.h>
#include <cstdint>

// Problem dims
static constexpr int BATCH = 16;
static constexpr int DIMD  = 512;
static constexpr int NN    = 2048;
static constexpr int NSAMP = 15;

// ---------------- scratch (device globals; no allocations allowed) ----------
__device__ float g_scores[(size_t)BATCH * NN * NN];   // 268 MB
__device__ float g_rowVal[BATCH * NN];
__device__ int   g_rowArg[BATCH * NN];
__device__ float g_colsum[BATCH * NN];
__device__ int   g_matchR[BATCH * NSAMP];
__device__ int   g_matchC[BATCH * NSAMP];

// bf16 split operands, K-major: [B][N][D]
__device__ __nv_bfloat16 g_Ah[(size_t)BATCH * NN * DIMD];
__device__ __nv_bfloat16 g_Al[(size_t)BATCH * NN * DIMD];
__device__ __nv_bfloat16 g_Bh[(size_t)BATCH * NN * DIMD];
__device__ __nv_bfloat16 g_Bl[(size_t)BATCH * NN * DIMD];

// ======================= PTX helpers (baseline PTX only, no sm_103a feats) ==
__device__ __forceinline__ uint32_t smem_u32(const void* p) {
    uint32_t a;
    asm("{ .reg .u64 t; cvta.to.shared.u64 t, %1; cvt.u32.u64 %0, t; }"
        : "=r"(a) : "l"(p));
    return a;
}
__device__ __forceinline__ void cp16(uint32_t dst, const void* src) {
    asm volatile("cp.async.cg.shared.global [%0], [%1], 16;" :: "r"(dst), "l"(src));
}
#define CP_COMMIT() asm volatile("cp.async.commit_group;" ::: "memory")
#define CP_WAIT(n)  asm volatile("cp.async.wait_group %0;" :: "n"(n) : "memory")

__device__ __forceinline__ void ldsm_x4(uint32_t& r0, uint32_t& r1,
                                        uint32_t& r2, uint32_t& r3, uint32_t addr) {
    asm volatile("ldmatrix.sync.aligned.m8n8.x4.shared.b16 {%0,%1,%2,%3}, [%4];"
                 : "=r"(r0), "=r"(r1), "=r"(r2), "=r"(r3) : "r"(addr));
}
__device__ __forceinline__ void mma16816(float* c, const uint32_t* a,
                                         uint32_t b0, uint32_t b1) {
    asm volatile("mma.sync.aligned.m16n8k16.row.col.f32.bf16.bf16.f32 "
                 "{%0,%1,%2,%3}, {%4,%5,%6,%7}, {%8,%9}, {%0,%1,%2,%3};"
                 : "+f"(c[0]), "+f"(c[1]), "+f"(c[2]), "+f"(c[3])
                 : "r"(a[0]), "r"(a[1]), "r"(a[2]), "r"(a[3]), "r"(b0), "r"(b1));
}

// ============ Kernel 0: transpose + bf16 split  [B,D,N] -> [B,N,D] hi/lo ====
__global__ __launch_bounds__(256) void convert_kernel(
    const float* __restrict__ E, __nv_bfloat16* __restrict__ Oh,
    __nv_bfloat16* __restrict__ Ol)
{
    __shared__ float tile[32][33];
    int b = blockIdx.z;
    int d0 = blockIdx.y * 32, n0 = blockIdx.x * 32;
    int tx = threadIdx.x & 31, ty = threadIdx.x >> 5;     // 32 x 8
    const float* Eb = E + (size_t)b * DIMD * NN;
#pragma unroll
    for (int i = 0; i < 4; i++) {
        int d = d0 + ty + i * 8;
        tile[ty + i * 8][tx] = Eb[(size_t)d * NN + n0 + tx];
    }
    __syncthreads();
    __nv_bfloat16* OhB = Oh + (size_t)b * NN * DIMD;
    __nv_bfloat16* OlB = Ol + (size_t)b * NN * DIMD;
#pragma unroll
    for (int i = 0; i < 4; i++) {
        int n = n0 + ty + i * 8;
        int d = d0 + tx;
        float v = tile[tx][ty + i * 8];
        __nv_bfloat16 hi = __float2bfloat16_rn(v);
        __nv_bfloat16 lo = __float2bfloat16_rn(v - __bfloat162float(hi));
        OhB[(size_t)n * DIMD + d] = hi;
        OlB[(size_t)n * DIMD + d] = lo;
    }
}

// ============ Kernel 1: HMMA bf16-split GEMM -> fp32 logits =================
// CTA tile 128x128, BK=32, 256 threads (8 warps, 4(m) x 2(n), warp 32x64).
// Double-buffered cp.async; 3 mma terms per (m,n,k16): AhBh + AlBh + AhBl.
static constexpr int BKC   = 32;                 // K per chunk
static constexpr int NKC   = DIMD / BKC;         // 16 chunks
static constexpr int STG   = 32768;              // 4 tiles x 8KB per stage
static constexpr int SM_GEMM_TOTAL = 2 * STG;    // 64 KB

// tile row = 64 bytes (32 bf16) = 4 x 16B chunks; swizzle chunk ^= (row>>1)&3
__device__ __forceinline__ uint32_t sw_off(int row, int c) {
    return (uint32_t)(row * 64 + ((c ^ ((row >> 1) & 3)) << 4));
}

__device__ __forceinline__ void load_stage(
    uint32_t stage_base, const __nv_bfloat16* Ahb, const __nv_bfloat16* Alb,
    const __nv_bfloat16* Bhb, const __nv_bfloat16* Blb, int k0, int tid)
{
    int t = tid >> 6;                 // 0..3 : which tile
    int sub = tid & 63;
    const __nv_bfloat16* base = (t == 0) ? Ahb : (t == 1) ? Alb : (t == 2) ? Bhb : Blb;
    uint32_t tbase = stage_base + t * 8192;
#pragma unroll
    for (int j = 0; j < 8; j++) {
        int ci = sub + j * 64;        // 0..511
        int row = ci >> 2, c = ci & 3;
        cp16(tbase + sw_off(row, c), base + (size_t)row * DIMD + k0 + c * 8);
    }
}

__global__ __launch_bounds__(256, 1) void gemm_hmma_kernel()
{
    extern __shared__ char smem[];
    uint32_t sm0 = smem_u32(smem);
    int tid = threadIdx.x;
    int wid = tid >> 5, lane = tid & 31;
    int wm = wid & 3;                  // 0..3
    int wn = wid >> 2;                 // 0..1
    int b  = blockIdx.z;
    int s0 = blockIdx.y * 128;
    int t0 = blockIdx.x * 128;

    const __nv_bfloat16* Ahb = g_Ah + ((size_t)b * NN + s0) * DIMD;
    const __nv_bfloat16* Alb = g_Al + ((size_t)b * NN + s0) * DIMD;
    const __nv_bfloat16* Bhb = g_Bh + ((size_t)b * NN + t0) * DIMD;
    const __nv_bfloat16* Blb = g_Bl + ((size_t)b * NN + t0) * DIMD;

    float acc[2][8][4];
#pragma unroll
    for (int i = 0; i < 2; i++)
#pragma unroll
        for (int j = 0; j < 8; j++)
#pragma unroll
            for (int k = 0; k < 4; k++) acc[i][j][k] = 0.f;

    // prologue
    load_stage(sm0, Ahb, Alb, Bhb, Blb, 0, tid);
    CP_COMMIT();

    for (int kc = 0; kc < NKC; kc++) {
        if (kc + 1 < NKC) {
            load_stage(sm0 + ((kc + 1) & 1) * STG, Ahb, Alb, Bhb, Blb,
                       (kc + 1) * BKC, tid);
            CP_COMMIT();
            CP_WAIT(1);
        } else {
            CP_WAIT(0);
        }
        __syncthreads();

        uint32_t sbase = sm0 + (kc & 1) * STG;
#pragma unroll
        for (int h = 0; h < 2; h++) {
            uint32_t ah[2][4], al[2][4];
            int lr = lane & 15, lc = h * 2 + (lane >> 4);
#pragma unroll
            for (int f = 0; f < 2; f++) {
                int r = wm * 32 + f * 16 + lr;
                uint32_t off = sw_off(r, lc);
                ldsm_x4(ah[f][0], ah[f][1], ah[f][2], ah[f][3], sbase + off);
                ldsm_x4(al[f][0], al[f][1], al[f][2], al[f][3], sbase + 8192 + off);
            }
#pragma unroll
            for (int g = 0; g < 4; g++) {
                int r = wn * 64 + g * 16 + lr;
                uint32_t off = sw_off(r, lc);
                uint32_t bh[4], bl[4];
                ldsm_x4(bh[0], bh[1], bh[2], bh[3], sbase + 16384 + off);
                ldsm_x4(bl[0], bl[1], bl[2], bl[3], sbase + 24576 + off);
#pragma unroll
                for (int f = 0; f < 2; f++) {
                    // n-frag 2g: B regs {x[0], x[2]}
                    mma16816(acc[f][2 * g],     ah[f], bh[0], bh[2]);
                    mma16816(acc[f][2 * g],     al[f], bh[0], bh[2]);
                    mma16816(acc[f][2 * g],     ah[f], bl[0], bl[2]);
                    // n-frag 2g+1: B regs {x[1], x[3]}
                    mma16816(acc[f][2 * g + 1], ah[f], bh[1], bh[3]);
                    mma16816(acc[f][2 * g + 1], al[f], bh[1], bh[3]);
                    mma16816(acc[f][2 * g + 1], ah[f], bl[1], bl[3]);
                }
            }
        }
        __syncthreads();
    }

    // Epilogue: C frag m16n8: (c0,c1)->row lane/4, cols 2*(lane%4); (c2,c3)->row+8
    const float scale = 0.044194173824159216f;   // 1/sqrt(512)
    float* Ob = g_scores + (size_t)b * NN * NN;
    int rbase = s0 + wm * 32 + (lane >> 2);
    int cbase = t0 + wn * 64 + 2 * (lane & 3);
#pragma unroll
    for (int f = 0; f < 2; f++) {
#pragma unroll
        for (int n = 0; n < 8; n++) {
            int r = rbase + f * 16;
            int cg = cbase + n * 8;
            float2 v0 = make_float2(acc[f][n][0] * scale, acc[f][n][1] * scale);
            float2 v1 = make_float2(acc[f][n][2] * scale, acc[f][n][3] * scale);
            *reinterpret_cast<float2*>(&Ob[(size_t)r * NN + cg])       = v0;
            *reinterpret_cast<float2*>(&Ob[(size_t)(r + 8) * NN + cg]) = v1;
        }
    }
}

// ---------------- Kernel 2: per-row softmax (in place) + row max/argmax -----
__global__ __launch_bounds__(256) void softmax_kernel()
{
    int row = blockIdx.x;                       // 0 .. B*N-1
    float* p = g_scores + (size_t)row * NN;
    __shared__ float rv[256];
    __shared__ int   ri[256];
    int tid = threadIdx.x;

    float m = -3.4e38f;
    for (int c = tid; c < NN; c += 256) { float v = p[c]; if (v > m) m = v; }
    rv[tid] = m; __syncthreads();
    for (int s = 128; s > 0; s >>= 1) {
        if (tid < s) { if (rv[tid + s] > rv[tid]) rv[tid] = rv[tid + s]; }
        __syncthreads();
    }
    float M = rv[0];
    __syncthreads();

    float sum = 0.f;
    for (int c = tid; c < NN; c += 256) sum += expf(p[c] - M);
    rv[tid] = sum; __syncthreads();
    for (int s = 128; s > 0; s >>= 1) {
        if (tid < s) rv[tid] += rv[tid + s];
        __syncthreads();
    }
    float inv = 1.0f / rv[0];
    __syncthreads();

    // write scores AND track max/argmax of stored values (tie -> smallest col)
    float mv = -1.f; int mc = 0;
    for (int c = tid; c < NN; c += 256) {
        float v = expf(p[c] - M) * inv;
        p[c] = v;
        if (v > mv) { mv = v; mc = c; }
    }
    rv[tid] = mv; ri[tid] = mc; __syncthreads();
    for (int s = 128; s > 0; s >>= 1) {
        if (tid < s) {
            float v2 = rv[tid + s]; int c2 = ri[tid + s];
            if (v2 > rv[tid] || (v2 == rv[tid] && c2 < ri[tid])) { rv[tid] = v2; ri[tid] = c2; }
        }
        __syncthreads();
    }
    if (tid == 0) { g_rowVal[row] = rv[0]; g_rowArg[row] = ri[0]; }
}

// ---------------- Kernel 3: column sums of scores ---------------------------
__global__ __launch_bounds__(256) void colsum_kernel()
{
    int b = blockIdx.y;
    int t = blockIdx.x * 256 + threadIdx.x;
    const float* sc = g_scores + (size_t)b * NN * NN;
    float s = 0.f;
    for (int r = 0; r < NN; r++) s += sc[(size_t)r * NN + t];
    g_colsum[b * NN + t] = s;
}

// ---------------- Kernel 4: greedy one-to-one matching ----------------------
__global__ __launch_bounds__(256) void match_kernel()
{
    int b = blockIdx.x;
    int tid = threadIdx.x;
    __shared__ float rVal[NN];
    __shared__ int   rArg[NN];
    __shared__ unsigned char colDead[NN];
    __shared__ float redV[256];
    __shared__ int   redI[256];
    __shared__ int   list[256];
    __shared__ int   listCnt;
    __shared__ int   selC;

    for (int i = tid; i < NN; i += 256) {
        rVal[i] = g_rowVal[b * NN + i];
        rArg[i] = g_rowArg[b * NN + i];
        colDead[i] = 0;
    }
    __syncthreads();

    const float* sc = g_scores + (size_t)b * NN * NN;

    for (int it = 0; it < NSAMP; it++) {
        float bv = -1.f; int br = 0;
        for (int r = tid; r < NN; r += 256) {
            float v = rVal[r];
            if (v > bv) { bv = v; br = r; }
        }
        redV[tid] = bv; redI[tid] = br; __syncthreads();
        for (int s = 128; s > 0; s >>= 1) {
            if (tid < s) {
                float v2 = redV[tid + s]; int r2 = redI[tid + s];
                if (v2 > redV[tid] || (v2 == redV[tid] && r2 < redI[tid])) {
                    redV[tid] = v2; redI[tid] = r2;
                }
            }
            __syncthreads();
        }
        if (tid == 0) {
            int r = redI[0];
            int c = rArg[r];
            g_matchR[b * NSAMP + it] = r;
            g_matchC[b * NSAMP + it] = c;
            rVal[r] = -1.f;
            colDead[c] = 1;
            selC = c;
            listCnt = 0;
        }
        __syncthreads();

        int c = selC;
        for (int r = tid; r < NN; r += 256) {
            if (rVal[r] >= 0.f && rArg[r] == c) {
                int pos = atomicAdd(&listCnt, 1);
                if (pos < 256) list[pos] = r;
            }
        }
        __syncthreads();
        int cnt = listCnt; if (cnt > 256) cnt = 256;
        for (int li = 0; li < cnt; li++) {
            int r = list[li];
            const float* rowp = sc + (size_t)r * NN;
            float mv = -1.f; int mc = 0;
            for (int cc = tid; cc < NN; cc += 256) {
                if (!colDead[cc]) {
                    float v = rowp[cc];
                    if (v > mv) { mv = v; mc = cc; }
                }
            }
            redV[tid] = mv; redI[tid] = mc; __syncthreads();
            for (int s = 128; s > 0; s >>= 1) {
                if (tid < s) {
                    float v2 = redV[tid + s]; int c2 = redI[tid + s];
                    if (v2 > redV[tid] || (v2 == redV[tid] && c2 < redI[tid])) {
                        redV[tid] = v2; redI[tid] = c2;
                    }
                }
                __syncthreads();
            }
            if (tid == 0) { rVal[r] = redV[0]; rArg[r] = redI[0]; }
            __syncthreads();
        }
        __syncthreads();
    }
}

// ---------------- Kernel 5: gather + centroids + 3x3 Kabsch SVD + output ----
__global__ __launch_bounds__(128) void finalize_kernel(
    const float* __restrict__ src, const float* __restrict__ tgt,
    float* __restrict__ out, int out_size)
{
    int b = blockIdx.x, tid = threadIdx.x;
    __shared__ float rx[128], ry[128], rz[128];
    __shared__ float srcMean[3], corrMean[3];
    __shared__ float sp[NSAMP][3], tp[NSAMP][3];

    const float* sb = src + (size_t)b * NN * 3;
    const float* tb = tgt + (size_t)b * NN * 3;

    float sx = 0, sy = 0, sz = 0;
    for (int n = tid; n < NN; n += 128) {
        sx += sb[3 * n]; sy += sb[3 * n + 1]; sz += sb[3 * n + 2];
    }
    rx[tid] = sx; ry[tid] = sy; rz[tid] = sz; __syncthreads();
    for (int s = 64; s > 0; s >>= 1) {
        if (tid < s) { rx[tid] += rx[tid + s]; ry[tid] += ry[tid + s]; rz[tid] += rz[tid + s]; }
        __syncthreads();
    }
    if (tid == 0) {
        srcMean[0] = rx[0] / NN; srcMean[1] = ry[0] / NN; srcMean[2] = rz[0] / NN;
    }
    __syncthreads();

    sx = sy = sz = 0;
    for (int n = tid; n < NN; n += 128) {
        float w = g_colsum[b * NN + n];
        sx += tb[3 * n] * w; sy += tb[3 * n + 1] * w; sz += tb[3 * n + 2] * w;
    }
    rx[tid] = sx; ry[tid] = sy; rz[tid] = sz; __syncthreads();
    for (int s = 64; s > 0; s >>= 1) {
        if (tid < s) { rx[tid] += rx[tid + s]; ry[tid] += ry[tid + s]; rz[tid] += rz[tid + s]; }
        __syncthreads();
    }
    if (tid == 0) {
        corrMean[0] = rx[0] / NN; corrMean[1] = ry[0] / NN; corrMean[2] = rz[0] / NN;
    }

    if (tid < NSAMP) {
        int r = g_matchR[b * NSAMP + tid];
        int c = g_matchC[b * NSAMP + tid];
        sp[tid][0] = sb[3 * r]; sp[tid][1] = sb[3 * r + 1]; sp[tid][2] = sb[3 * r + 2];
        tp[tid][0] = tb[3 * c]; tp[tid][1] = tb[3 * c + 1]; tp[tid][2] = tb[3 * c + 2];
    }
    __syncthreads();

    if (tid == 0) {
        double ms[3] = {0, 0, 0}, mt[3] = {0, 0, 0};
        for (int s = 0; s < NSAMP; s++)
            for (int i = 0; i < 3; i++) { ms[i] += sp[s][i]; mt[i] += tp[s][i]; }
        for (int i = 0; i < 3; i++) { ms[i] /= NSAMP; mt[i] /= NSAMP; }

        double H[3][3] = {};
        for (int s = 0; s < NSAMP; s++)
            for (int i = 0; i < 3; i++)
                for (int j = 0; j < 3; j++)
                    H[i][j] += ((double)sp[s][i] - ms[i]) * ((double)tp[s][j] - mt[j]);

        double Sm[3][3];
        for (int i = 0; i < 3; i++)
            for (int j = 0; j < 3; j++) {
                double acc = 0;
                for (int k = 0; k < 3; k++) acc += H[k][i] * H[k][j];
                Sm[i][j] = acc;
            }
        double V[3][3] = {{1, 0, 0}, {0, 1, 0}, {0, 0, 1}};
        for (int sweep = 0; sweep < 12; sweep++) {
            for (int pi = 0; pi < 3; pi++) {
                for (int qi = pi + 1; qi < 3; qi++) {
                    double apq = Sm[pi][qi];
                    if (fabs(apq) < 1e-30) continue;
                    double app = Sm[pi][pi], aqq = Sm[qi][qi];
                    double theta = 0.5 * (aqq - app) / apq;
                    double tJ = ((theta >= 0) ? 1.0 : -1.0) /
                                (fabs(theta) + sqrt(theta * theta + 1.0));
                    double cJ = 1.0 / sqrt(tJ * tJ + 1.0);
                    double sJ = tJ * cJ;
                    for (int k = 0; k < 3; k++) {
                        double skp = Sm[k][pi], skq = Sm[k][qi];
                        Sm[k][pi] = cJ * skp - sJ * skq;
                        Sm[k][qi] = sJ * skp + cJ * skq;
                    }
                    for (int k = 0; k < 3; k++) {
                        double spk = Sm[pi][k], sqk = Sm[qi][k];
                        Sm[pi][k] = cJ * spk - sJ * sqk;
                        Sm[qi][k] = sJ * spk + cJ * sqk;
                    }
                    for (int k = 0; k < 3; k++) {
                        double vkp = V[k][pi], vkq = V[k][qi];
                        V[k][pi] = cJ * vkp - sJ * vkq;
                        V[k][qi] = sJ * vkp + cJ * vkq;
                    }
                }
            }
        }
        double lam[3] = {Sm[0][0], Sm[1][1], Sm[2][2]};
        int idx[3] = {0, 1, 2};
        for (int i = 0; i < 2; i++)
            for (int j = i + 1; j < 3; j++)
                if (lam[idx[j]] > lam[idx[i]]) { int t2 = idx[i]; idx[i] = idx[j]; idx[j] = t2; }
        double Vc[3][3], U[3][3];
        for (int k = 0; k < 3; k++) {
            int c = idx[k];
            double sig = sqrt(lam[c] > 0 ? lam[c] : 0);
            double invs = (sig > 1e-300) ? 1.0 / sig : 0.0;
            for (int i = 0; i < 3; i++) Vc[i][k] = V[i][c];
            for (int i = 0; i < 3; i++) {
                double acc = 0;
                for (int j = 0; j < 3; j++) acc += H[i][j] * Vc[j][k];
                U[i][k] = acc * invs;
            }
        }
        double R[3][3];
        for (int i = 0; i < 3; i++)
            for (int j = 0; j < 3; j++) {
                double acc = 0;
                for (int k = 0; k < 3; k++) acc += Vc[i][k] * U[j][k];
                R[i][j] = acc;
            }
        double det =
            R[0][0] * (R[1][1] * R[2][2] - R[1][2] * R[2][1]) -
            R[0][1] * (R[1][0] * R[2][2] - R[1][2] * R[2][0]) +
            R[0][2] * (R[1][0] * R[2][1] - R[1][1] * R[2][0]);
        if (det < 0) {
            for (int i = 0; i < 3; i++)
                for (int j = 0; j < 3; j++)
                    R[i][j] -= 2.0 * Vc[i][2] * U[j][2];
        }
        double tv[3];
        for (int i = 0; i < 3; i++) {
            double acc = 0;
            for (int j = 0; j < 3; j++) acc += R[i][j] * (double)srcMean[j];
            tv[i] = -acc + (double)corrMean[i];
        }
        for (int i = 0; i < 3; i++)
            for (int j = 0; j < 3; j++)
                out[b * 9 + i * 3 + j] = (float)R[i][j];
        if (out_size >= BATCH * 9 + BATCH * 3) {
            for (int i = 0; i < 3; i++)
                out[BATCH * 9 + b * 3 + i] = (float)tv[i];
        }
    }
}

// ---------------- launch ----------------
extern "C" void kernel_launch(void* const* d_in, const int* in_sizes, int n_in,
                              void* d_out, int out_size)
{
    const float* src_emb = (const float*)d_in[0];
    const float* tgt_emb = (const float*)d_in[1];
    const float* src     = (const float*)d_in[2];
    const float* tgt     = (const float*)d_in[3];
    float* out = (float*)d_out;

    cudaFuncSetAttribute(gemm_hmma_kernel,
                         cudaFuncAttributeMaxDynamicSharedMemorySize, SM_GEMM_TOTAL);

    __nv_bfloat16 *pAh, *pAl, *pBh, *pBl;
    cudaGetSymbolAddress((void**)&pAh, g_Ah);
    cudaGetSymbolAddress((void**)&pAl, g_Al);
    cudaGetSymbolAddress((void**)&pBh, g_Bh);
    cudaGetSymbolAddress((void**)&pBl, g_Bl);

    dim3 gConv(NN / 32, DIMD / 32, BATCH);
    convert_kernel<<<gConv, 256>>>(src_emb, pAh, pAl);
    convert_kernel<<<gConv, 256>>>(tgt_emb, pBh, pBl);

    dim3 gGemm(NN / 128, NN / 128, BATCH);
    gemm_hmma_kernel<<<gGemm, 256, SM_GEMM_TOTAL>>>();

    softmax_kernel<<<BATCH * NN, 256>>>();

    dim3 gCol(NN / 256, BATCH);
    colsum_kernel<<<gCol, 256>>>();

    match_kernel<<<BATCH, 256>>>();

    finalize_kernel<<<BATCH, 128>>>(src, tgt, out, out_size);
}

// round 12
// speedup vs baseline: 2.3112x; 1.1790x over previous
#include <cuda_runtime.h>
#include <cuda_bf16.h>
#include <math.h>
#include <cstdint>

// Problem dims
static constexpr int BATCH = 16;
static constexpr int DIMD  = 512;
static constexpr int NN    = 2048;
static constexpr int NSAMP = 15;
static constexpr int CSPLIT = 16;     // colsum row splits

// ---------------- scratch (device globals; no allocations allowed) ----------
__device__ float g_scores[(size_t)BATCH * NN * NN];   // 268 MB
__device__ float g_rowVal[BATCH * NN];
__device__ int   g_rowArg[BATCH * NN];
__device__ float g_colsum[BATCH * NN];
__device__ float g_colpart[(size_t)CSPLIT * BATCH * NN];
__device__ int   g_matchR[BATCH * NSAMP];
__device__ int   g_matchC[BATCH * NSAMP];

// bf16 split operands, K-major: [B][N][D]
__device__ __nv_bfloat16 g_Ah[(size_t)BATCH * NN * DIMD];
__device__ __nv_bfloat16 g_Al[(size_t)BATCH * NN * DIMD];
__device__ __nv_bfloat16 g_Bh[(size_t)BATCH * NN * DIMD];
__device__ __nv_bfloat16 g_Bl[(size_t)BATCH * NN * DIMD];

// ======================= PTX helpers (baseline PTX only) ====================
__device__ __forceinline__ uint32_t smem_u32(const void* p) {
    uint32_t a;
    asm("{ .reg .u64 t; cvta.to.shared.u64 t, %1; cvt.u32.u64 %0, t; }"
        : "=r"(a) : "l"(p));
    return a;
}
__device__ __forceinline__ void cp16(uint32_t dst, const void* src) {
    asm volatile("cp.async.cg.shared.global [%0], [%1], 16;" :: "r"(dst), "l"(src));
}
#define CP_COMMIT() asm volatile("cp.async.commit_group;" ::: "memory")
#define CP_WAIT(n)  asm volatile("cp.async.wait_group %0;" :: "n"(n) : "memory")

__device__ __forceinline__ void ldsm_x4(uint32_t& r0, uint32_t& r1,
                                        uint32_t& r2, uint32_t& r3, uint32_t addr) {
    asm volatile("ldmatrix.sync.aligned.m8n8.x4.shared.b16 {%0,%1,%2,%3}, [%4];"
                 : "=r"(r0), "=r"(r1), "=r"(r2), "=r"(r3) : "r"(addr));
}
__device__ __forceinline__ void mma16816(float* c, const uint32_t* a,
                                         uint32_t b0, uint32_t b1) {
    asm volatile("mma.sync.aligned.m16n8k16.row.col.f32.bf16.bf16.f32 "
                 "{%0,%1,%2,%3}, {%4,%5,%6,%7}, {%8,%9}, {%0,%1,%2,%3};"
                 : "+f"(c[0]), "+f"(c[1]), "+f"(c[2]), "+f"(c[3])
                 : "r"(a[0]), "r"(a[1]), "r"(a[2]), "r"(a[3]), "r"(b0), "r"(b1));
}

// ============ Kernel 0: transpose + bf16 split  [B,D,N] -> [B,N,D] hi/lo ====
__global__ __launch_bounds__(256) void convert_kernel(
    const float* __restrict__ E, __nv_bfloat16* __restrict__ Oh,
    __nv_bfloat16* __restrict__ Ol)
{
    __shared__ float tile[32][33];
    int b = blockIdx.z;
    int d0 = blockIdx.y * 32, n0 = blockIdx.x * 32;
    int tx = threadIdx.x & 31, ty = threadIdx.x >> 5;     // 32 x 8
    const float* Eb = E + (size_t)b * DIMD * NN;
#pragma unroll
    for (int i = 0; i < 4; i++) {
        int d = d0 + ty + i * 8;
        tile[ty + i * 8][tx] = Eb[(size_t)d * NN + n0 + tx];
    }
    __syncthreads();
    __nv_bfloat16* OhB = Oh + (size_t)b * NN * DIMD;
    __nv_bfloat16* OlB = Ol + (size_t)b * NN * DIMD;
#pragma unroll
    for (int i = 0; i < 4; i++) {
        int n = n0 + ty + i * 8;
        int d = d0 + tx;
        float v = tile[tx][ty + i * 8];
        __nv_bfloat16 hi = __float2bfloat16_rn(v);
        __nv_bfloat16 lo = __float2bfloat16_rn(v - __bfloat162float(hi));
        OhB[(size_t)n * DIMD + d] = hi;
        OlB[(size_t)n * DIMD + d] = lo;
    }
}

// ============ Kernel 1: HMMA bf16-split GEMM -> fp32 logits =================
// CTA tile 128x128, BK=32, 256 threads (8 warps, 4(m) x 2(n), warp 32x64).
// Double-buffered cp.async; 3 mma terms per (m,n,k16): AhBh + AlBh + AhBl.
static constexpr int BKC   = 32;                 // K per chunk
static constexpr int NKC   = DIMD / BKC;         // 16 chunks
static constexpr int STG   = 32768;              // 4 tiles x 8KB per stage
static constexpr int SM_GEMM_TOTAL = 2 * STG;    // 64 KB

// tile row = 64 bytes (32 bf16) = 4 x 16B chunks; swizzle chunk ^= (row>>1)&3
__device__ __forceinline__ uint32_t sw_off(int row, int c) {
    return (uint32_t)(row * 64 + ((c ^ ((row >> 1) & 3)) << 4));
}

__device__ __forceinline__ void load_stage(
    uint32_t stage_base, const __nv_bfloat16* Ahb, const __nv_bfloat16* Alb,
    const __nv_bfloat16* Bhb, const __nv_bfloat16* Blb, int k0, int tid)
{
    int t = tid >> 6;                 // 0..3 : which tile
    int sub = tid & 63;
    const __nv_bfloat16* base = (t == 0) ? Ahb : (t == 1) ? Alb : (t == 2) ? Bhb : Blb;
    uint32_t tbase = stage_base + t * 8192;
#pragma unroll
    for (int j = 0; j < 8; j++) {
        int ci = sub + j * 64;        // 0..511
        int row = ci >> 2, c = ci & 3;
        cp16(tbase + sw_off(row, c), base + (size_t)row * DIMD + k0 + c * 8);
    }
}

__global__ __launch_bounds__(256, 2) void gemm_hmma_kernel()
{
    extern __shared__ char smem[];
    uint32_t sm0 = smem_u32(smem);
    int tid = threadIdx.x;
    int wid = tid >> 5, lane = tid & 31;
    int wm = wid & 3;                  // 0..3
    int wn = wid >> 2;                 // 0..1
    int b  = blockIdx.z;
    int s0 = blockIdx.y * 128;
    int t0 = blockIdx.x * 128;

    const __nv_bfloat16* Ahb = g_Ah + ((size_t)b * NN + s0) * DIMD;
    const __nv_bfloat16* Alb = g_Al + ((size_t)b * NN + s0) * DIMD;
    const __nv_bfloat16* Bhb = g_Bh + ((size_t)b * NN + t0) * DIMD;
    const __nv_bfloat16* Blb = g_Bl + ((size_t)b * NN + t0) * DIMD;

    float acc[2][8][4];
#pragma unroll
    for (int i = 0; i < 2; i++)
#pragma unroll
        for (int j = 0; j < 8; j++)
#pragma unroll
            for (int k = 0; k < 4; k++) acc[i][j][k] = 0.f;

    // prologue
    load_stage(sm0, Ahb, Alb, Bhb, Blb, 0, tid);
    CP_COMMIT();

    for (int kc = 0; kc < NKC; kc++) {
        if (kc + 1 < NKC) {
            load_stage(sm0 + ((kc + 1) & 1) * STG, Ahb, Alb, Bhb, Blb,
                       (kc + 1) * BKC, tid);
            CP_COMMIT();
            CP_WAIT(1);
        } else {
            CP_WAIT(0);
        }
        __syncthreads();

        uint32_t sbase = sm0 + (kc & 1) * STG;
#pragma unroll
        for (int h = 0; h < 2; h++) {
            uint32_t ah[2][4], al[2][4];
            int lr = lane & 15, lc = h * 2 + (lane >> 4);
#pragma unroll
            for (int f = 0; f < 2; f++) {
                int r = wm * 32 + f * 16 + lr;
                uint32_t off = sw_off(r, lc);
                ldsm_x4(ah[f][0], ah[f][1], ah[f][2], ah[f][3], sbase + off);
                ldsm_x4(al[f][0], al[f][1], al[f][2], al[f][3], sbase + 8192 + off);
            }
#pragma unroll
            for (int g = 0; g < 4; g++) {
                int r = wn * 64 + g * 16 + lr;
                uint32_t off = sw_off(r, lc);
                uint32_t bh[4], bl[4];
                ldsm_x4(bh[0], bh[1], bh[2], bh[3], sbase + 16384 + off);
                ldsm_x4(bl[0], bl[1], bl[2], bl[3], sbase + 24576 + off);
#pragma unroll
                for (int f = 0; f < 2; f++) {
                    mma16816(acc[f][2 * g],     ah[f], bh[0], bh[2]);
                    mma16816(acc[f][2 * g],     al[f], bh[0], bh[2]);
                    mma16816(acc[f][2 * g],     ah[f], bl[0], bl[2]);
                    mma16816(acc[f][2 * g + 1], ah[f], bh[1], bh[3]);
                    mma16816(acc[f][2 * g + 1], al[f], bh[1], bh[3]);
                    mma16816(acc[f][2 * g + 1], ah[f], bl[1], bl[3]);
                }
            }
        }
        __syncthreads();
    }

    // Epilogue: C frag m16n8: (c0,c1)->row lane/4, cols 2*(lane%4); (c2,c3)->row+8
    const float scale = 0.044194173824159216f;   // 1/sqrt(512)
    float* Ob = g_scores + (size_t)b * NN * NN;
    int rbase = s0 + wm * 32 + (lane >> 2);
    int cbase = t0 + wn * 64 + 2 * (lane & 3);
#pragma unroll
    for (int f = 0; f < 2; f++) {
#pragma unroll
        for (int n = 0; n < 8; n++) {
            int r = rbase + f * 16;
            int cg = cbase + n * 8;
            float2 v0 = make_float2(acc[f][n][0] * scale, acc[f][n][1] * scale);
            float2 v1 = make_float2(acc[f][n][2] * scale, acc[f][n][3] * scale);
            *reinterpret_cast<float2*>(&Ob[(size_t)r * NN + cg])       = v0;
            *reinterpret_cast<float2*>(&Ob[(size_t)(r + 8) * NN + cg]) = v1;
        }
    }
}

// ---------------- Kernel 2: single-pass register-resident softmax -----------
// One block per row; 256 threads x 8 elements (2 x float4). One read, one write.
__global__ __launch_bounds__(256) void softmax_kernel()
{
    int row = blockIdx.x;                       // 0 .. B*N-1
    float* p = g_scores + (size_t)row * NN;
    int tid = threadIdx.x;
    int lane = tid & 31, warp = tid >> 5;
    __shared__ float wred[8];
    __shared__ int   wredi[8];

    float4 v0 = reinterpret_cast<const float4*>(p)[tid * 2];
    float4 v1 = reinterpret_cast<const float4*>(p)[tid * 2 + 1];
    float vals[8] = {v0.x, v0.y, v0.z, v0.w, v1.x, v1.y, v1.z, v1.w};

    // 1) row max
    float m = vals[0];
#pragma unroll
    for (int j = 1; j < 8; j++) m = fmaxf(m, vals[j]);
#pragma unroll
    for (int s = 16; s > 0; s >>= 1) m = fmaxf(m, __shfl_xor_sync(~0u, m, s));
    if (lane == 0) wred[warp] = m;
    __syncthreads();
    if (warp == 0) {
        float t = (lane < 8) ? wred[lane] : -3.4e38f;
#pragma unroll
        for (int s = 4; s > 0; s >>= 1) t = fmaxf(t, __shfl_xor_sync(~0u, t, s));
        if (lane == 0) wred[0] = t;
    }
    __syncthreads();
    float M = wred[0];
    __syncthreads();

    // 2) exp + sum (exp kept in registers)
    float ev[8];
    float sum = 0.f;
#pragma unroll
    for (int j = 0; j < 8; j++) { ev[j] = __expf(vals[j] - M); sum += ev[j]; }
#pragma unroll
    for (int s = 16; s > 0; s >>= 1) sum += __shfl_xor_sync(~0u, sum, s);
    if (lane == 0) wred[warp] = sum;
    __syncthreads();
    if (warp == 0) {
        float t = (lane < 8) ? wred[lane] : 0.f;
#pragma unroll
        for (int s = 4; s > 0; s >>= 1) t += __shfl_xor_sync(~0u, t, s);
        if (lane == 0) wred[0] = t;
    }
    __syncthreads();
    float inv = 1.0f / wred[0];
    __syncthreads();

    // 3) scale, store, and argmax of STORED values (tie -> smallest col)
    float sv[8];
#pragma unroll
    for (int j = 0; j < 8; j++) sv[j] = ev[j] * inv;
    reinterpret_cast<float4*>(p)[tid * 2]     = make_float4(sv[0], sv[1], sv[2], sv[3]);
    reinterpret_cast<float4*>(p)[tid * 2 + 1] = make_float4(sv[4], sv[5], sv[6], sv[7]);

    float mv = sv[0]; int mc = tid * 8;
#pragma unroll
    for (int j = 1; j < 8; j++)
        if (sv[j] > mv) { mv = sv[j]; mc = tid * 8 + j; }
#pragma unroll
    for (int s = 16; s > 0; s >>= 1) {
        float ov = __shfl_xor_sync(~0u, mv, s);
        int   oc = __shfl_xor_sync(~0u, mc, s);
        if (ov > mv || (ov == mv && oc < mc)) { mv = ov; mc = oc; }
    }
    if (lane == 0) { wred[warp] = mv; wredi[warp] = mc; }
    __syncthreads();
    if (warp == 0) {
        float t = (lane < 8) ? wred[lane] : -1.f;
        int   c = (lane < 8) ? wredi[lane] : 0;
#pragma unroll
        for (int s = 4; s > 0; s >>= 1) {
            float ov = __shfl_xor_sync(~0u, t, s);
            int   oc = __shfl_xor_sync(~0u, c, s);
            if (ov > t || (ov == t && oc < c)) { t = ov; c = oc; }
        }
        if (lane == 0) { g_rowVal[row] = t; g_rowArg[row] = c; }
    }
}

// ---------------- Kernel 3a: split-K column partial sums --------------------
// grid (2, BATCH, CSPLIT); each thread sums 4 cols (float4) over 128 rows.
__global__ __launch_bounds__(256) void colsum_part_kernel()
{
    int b = blockIdx.y;
    int z = blockIdx.z;
    int c4 = blockIdx.x * 256 + threadIdx.x;           // float4 index, 0..511
    const float* sc = g_scores + (size_t)b * NN * NN + z * 128 * NN;
    float4 s = make_float4(0.f, 0.f, 0.f, 0.f);
    for (int r = 0; r < 128; r++) {
        float4 v = reinterpret_cast<const float4*>(sc + (size_t)r * NN)[c4];
        s.x += v.x; s.y += v.y; s.z += v.z; s.w += v.w;
    }
    reinterpret_cast<float4*>(g_colpart + ((size_t)z * BATCH + b) * NN)[c4] = s;
}

// ---------------- Kernel 3b: reduce partials --------------------------------
__global__ __launch_bounds__(256) void colsum_reduce_kernel()
{
    int i = blockIdx.x * 256 + threadIdx.x;            // 0 .. BATCH*NN-1
    int b = i >> 11, c = i & (NN - 1);
    float s = 0.f;
    for (int z = 0; z < CSPLIT; z++)
        s += g_colpart[((size_t)z * BATCH + b) * NN + c];
    g_colsum[i] = s;
}

// ---------------- Kernel 4: greedy one-to-one matching ----------------------
__global__ __launch_bounds__(256) void match_kernel()
{
    int b = blockIdx.x;
    int tid = threadIdx.x;
    __shared__ float rVal[NN];
    __shared__ int   rArg[NN];
    __shared__ unsigned char colDead[NN];
    __shared__ float redV[256];
    __shared__ int   redI[256];
    __shared__ int   list[256];
    __shared__ int   listCnt;
    __shared__ int   selC;

    for (int i = tid; i < NN; i += 256) {
        rVal[i] = g_rowVal[b * NN + i];
        rArg[i] = g_rowArg[b * NN + i];
        colDead[i] = 0;
    }
    __syncthreads();

    const float* sc = g_scores + (size_t)b * NN * NN;

    for (int it = 0; it < NSAMP; it++) {
        float bv = -1.f; int br = 0;
        for (int r = tid; r < NN; r += 256) {
            float v = rVal[r];
            if (v > bv) { bv = v; br = r; }
        }
        redV[tid] = bv; redI[tid] = br; __syncthreads();
        for (int s = 128; s > 0; s >>= 1) {
            if (tid < s) {
                float v2 = redV[tid + s]; int r2 = redI[tid + s];
                if (v2 > redV[tid] || (v2 == redV[tid] && r2 < redI[tid])) {
                    redV[tid] = v2; redI[tid] = r2;
                }
            }
            __syncthreads();
        }
        if (tid == 0) {
            int r = redI[0];
            int c = rArg[r];
            g_matchR[b * NSAMP + it] = r;
            g_matchC[b * NSAMP + it] = c;
            rVal[r] = -1.f;
            colDead[c] = 1;
            selC = c;
            listCnt = 0;
        }
        __syncthreads();

        int c = selC;
        for (int r = tid; r < NN; r += 256) {
            if (rVal[r] >= 0.f && rArg[r] == c) {
                int pos = atomicAdd(&listCnt, 1);
                if (pos < 256) list[pos] = r;
            }
        }
        __syncthreads();
        int cnt = listCnt; if (cnt > 256) cnt = 256;
        for (int li = 0; li < cnt; li++) {
            int r = list[li];
            const float* rowp = sc + (size_t)r * NN;
            float mv = -1.f; int mc = 0;
            for (int cc = tid; cc < NN; cc += 256) {
                if (!colDead[cc]) {
                    float v = rowp[cc];
                    if (v > mv) { mv = v; mc = cc; }
                }
            }
            redV[tid] = mv; redI[tid] = mc; __syncthreads();
            for (int s = 128; s > 0; s >>= 1) {
                if (tid < s) {
                    float v2 = redV[tid + s]; int c2 = redI[tid + s];
                    if (v2 > redV[tid] || (v2 == redV[tid] && c2 < redI[tid])) {
                        redV[tid] = v2; redI[tid] = c2;
                    }
                }
                __syncthreads();
            }
            if (tid == 0) { rVal[r] = redV[0]; rArg[r] = redI[0]; }
            __syncthreads();
        }
        __syncthreads();
    }
}

// ---------------- Kernel 5: gather + centroids + 3x3 Kabsch SVD + output ----
__global__ __launch_bounds__(128) void finalize_kernel(
    const float* __restrict__ src, const float* __restrict__ tgt,
    float* __restrict__ out, int out_size)
{
    int b = blockIdx.x, tid = threadIdx.x;
    __shared__ float rx[128], ry[128], rz[128];
    __shared__ float srcMean[3], corrMean[3];
    __shared__ float sp[NSAMP][3], tp[NSAMP][3];

    const float* sb = src + (size_t)b * NN * 3;
    const float* tb = tgt + (size_t)b * NN * 3;

    float sx = 0, sy = 0, sz = 0;
    for (int n = tid; n < NN; n += 128) {
        sx += sb[3 * n]; sy += sb[3 * n + 1]; sz += sb[3 * n + 2];
    }
    rx[tid] = sx; ry[tid] = sy; rz[tid] = sz; __syncthreads();
    for (int s = 64; s > 0; s >>= 1) {
        if (tid < s) { rx[tid] += rx[tid + s]; ry[tid] += ry[tid + s]; rz[tid] += rz[tid + s]; }
        __syncthreads();
    }
    if (tid == 0) {
        srcMean[0] = rx[0] / NN; srcMean[1] = ry[0] / NN; srcMean[2] = rz[0] / NN;
    }
    __syncthreads();

    sx = sy = sz = 0;
    for (int n = tid; n < NN; n += 128) {
        float w = g_colsum[b * NN + n];
        sx += tb[3 * n] * w; sy += tb[3 * n + 1] * w; sz += tb[3 * n + 2] * w;
    }
    rx[tid] = sx; ry[tid] = sy; rz[tid] = sz; __syncthreads();
    for (int s = 64; s > 0; s >>= 1) {
        if (tid < s) { rx[tid] += rx[tid + s]; ry[tid] += ry[tid + s]; rz[tid] += rz[tid + s]; }
        __syncthreads();
    }
    if (tid == 0) {
        corrMean[0] = rx[0] / NN; corrMean[1] = ry[0] / NN; corrMean[2] = rz[0] / NN;
    }

    if (tid < NSAMP) {
        int r = g_matchR[b * NSAMP + tid];
        int c = g_matchC[b * NSAMP + tid];
        sp[tid][0] = sb[3 * r]; sp[tid][1] = sb[3 * r + 1]; sp[tid][2] = sb[3 * r + 2];
        tp[tid][0] = tb[3 * c]; tp[tid][1] = tb[3 * c + 1]; tp[tid][2] = tb[3 * c + 2];
    }
    __syncthreads();

    if (tid == 0) {
        double ms[3] = {0, 0, 0}, mt[3] = {0, 0, 0};
        for (int s = 0; s < NSAMP; s++)
            for (int i = 0; i < 3; i++) { ms[i] += sp[s][i]; mt[i] += tp[s][i]; }
        for (int i = 0; i < 3; i++) { ms[i] /= NSAMP; mt[i] /= NSAMP; }

        double H[3][3] = {};
        for (int s = 0; s < NSAMP; s++)
            for (int i = 0; i < 3; i++)
                for (int j = 0; j < 3; j++)
                    H[i][j] += ((double)sp[s][i] - ms[i]) * ((double)tp[s][j] - mt[j]);

        double Sm[3][3];
        for (int i = 0; i < 3; i++)
            for (int j = 0; j < 3; j++) {
                double acc = 0;
                for (int k = 0; k < 3; k++) acc += H[k][i] * H[k][j];
                Sm[i][j] = acc;
            }
        double V[3][3] = {{1, 0, 0}, {0, 1, 0}, {0, 0, 1}};
        for (int sweep = 0; sweep < 12; sweep++) {
            for (int pi = 0; pi < 3; pi++) {
                for (int qi = pi + 1; qi < 3; qi++) {
                    double apq = Sm[pi][qi];
                    if (fabs(apq) < 1e-30) continue;
                    double app = Sm[pi][pi], aqq = Sm[qi][qi];
                    double theta = 0.5 * (aqq - app) / apq;
                    double tJ = ((theta >= 0) ? 1.0 : -1.0) /
                                (fabs(theta) + sqrt(theta * theta + 1.0));
                    double cJ = 1.0 / sqrt(tJ * tJ + 1.0);
                    double sJ = tJ * cJ;
                    for (int k = 0; k < 3; k++) {
                        double skp = Sm[k][pi], skq = Sm[k][qi];
                        Sm[k][pi] = cJ * skp - sJ * skq;
                        Sm[k][qi] = sJ * skp + cJ * skq;
                    }
                    for (int k = 0; k < 3; k++) {
                        double spk = Sm[pi][k], sqk = Sm[qi][k];
                        Sm[pi][k] = cJ * spk - sJ * sqk;
                        Sm[qi][k] = sJ * spk + cJ * sqk;
                    }
                    for (int k = 0; k < 3; k++) {
                        double vkp = V[k][pi], vkq = V[k][qi];
                        V[k][pi] = cJ * vkp - sJ * vkq;
                        V[k][qi] = sJ * vkp + cJ * vkq;
                    }
                }
            }
        }
        double lam[3] = {Sm[0][0], Sm[1][1], Sm[2][2]};
        int idx[3] = {0, 1, 2};
        for (int i = 0; i < 2; i++)
            for (int j = i + 1; j < 3; j++)
                if (lam[idx[j]] > lam[idx[i]]) { int t2 = idx[i]; idx[i] = idx[j]; idx[j] = t2; }
        double Vc[3][3], U[3][3];
        for (int k = 0; k < 3; k++) {
            int c = idx[k];
            double sig = sqrt(lam[c] > 0 ? lam[c] : 0);
            double invs = (sig > 1e-300) ? 1.0 / sig : 0.0;
            for (int i = 0; i < 3; i++) Vc[i][k] = V[i][c];
            for (int i = 0; i < 3; i++) {
                double acc = 0;
                for (int j = 0; j < 3; j++) acc += H[i][j] * Vc[j][k];
                U[i][k] = acc * invs;
            }
        }
        double R[3][3];
        for (int i = 0; i < 3; i++)
            for (int j = 0; j < 3; j++) {
                double acc = 0;
                for (int k = 0; k < 3; k++) acc += Vc[i][k] * U[j][k];
                R[i][j] = acc;
            }
        double det =
            R[0][0] * (R[1][1] * R[2][2] - R[1][2] * R[2][1]) -
            R[0][1] * (R[1][0] * R[2][2] - R[1][2] * R[2][0]) +
            R[0][2] * (R[1][0] * R[2][1] - R[1][1] * R[2][0]);
        if (det < 0) {
            for (int i = 0; i < 3; i++)
                for (int j = 0; j < 3; j++)
                    R[i][j] -= 2.0 * Vc[i][2] * U[j][2];
        }
        double tv[3];
        for (int i = 0; i < 3; i++) {
            double acc = 0;
            for (int j = 0; j < 3; j++) acc += R[i][j] * (double)srcMean[j];
            tv[i] = -acc + (double)corrMean[i];
        }
        for (int i = 0; i < 3; i++)
            for (int j = 0; j < 3; j++)
                out[b * 9 + i * 3 + j] = (float)R[i][j];
        if (out_size >= BATCH * 9 + BATCH * 3) {
            for (int i = 0; i < 3; i++)
                out[BATCH * 9 + b * 3 + i] = (float)tv[i];
        }
    }
}

// ---------------- launch ----------------
extern "C" void kernel_launch(void* const* d_in, const int* in_sizes, int n_in,
                              void* d_out, int out_size)
{
    const float* src_emb = (const float*)d_in[0];
    const float* tgt_emb = (const float*)d_in[1];
    const float* src     = (const float*)d_in[2];
    const float* tgt     = (const float*)d_in[3];
    float* out = (float*)d_out;

    cudaFuncSetAttribute(gemm_hmma_kernel,
                         cudaFuncAttributeMaxDynamicSharedMemorySize, SM_GEMM_TOTAL);

    __nv_bfloat16 *pAh, *pAl, *pBh, *pBl;
    cudaGetSymbolAddress((void**)&pAh, g_Ah);
    cudaGetSymbolAddress((void**)&pAl, g_Al);
    cudaGetSymbolAddress((void**)&pBh, g_Bh);
    cudaGetSymbolAddress((void**)&pBl, g_Bl);

    dim3 gConv(NN / 32, DIMD / 32, BATCH);
    convert_kernel<<<gConv, 256>>>(src_emb, pAh, pAl);
    convert_kernel<<<gConv, 256>>>(tgt_emb, pBh, pBl);

    dim3 gGemm(NN / 128, NN / 128, BATCH);
    gemm_hmma_kernel<<<gGemm, 256, SM_GEMM_TOTAL>>>();

    softmax_kernel<<<BATCH * NN, 256>>>();

    dim3 gColP(2, BATCH, CSPLIT);
    colsum_part_kernel<<<gColP, 256>>>();
    colsum_reduce_kernel<<<(BATCH * NN) / 256, 256>>>();

    match_kernel<<<BATCH, 256>>>();

    finalize_kernel<<<BATCH, 128>>>(src, tgt, out, out_size);
}